// round 8
// baseline (speedup 1.0000x reference)
#include <cuda_runtime.h>
#include <cuda_bf16.h>

// ---------------------------------------------------------------------------
// BiLSTM-CRF forward loss.  B=64, T=512, V=50000, E=256, H=256, L=9.
// embed -> gemm(gx,l0) -> lstm(l0, 8-CTA clusters, per-slice pipelined sync)
//       -> gemm(gx,l1) -> lstm(l1) -> linear -> CRF NLL -> mean.
// ---------------------------------------------------------------------------

#define Bsz  64
#define Tlen 512
#define Emb  256
#define Hd   256
#define Lnum 9
#define BT   (Bsz * Tlen)   // 32768

// dynamic smem layout for k_lstm (float offsets)
#define SM_W    0          // [32768]  w slice (rank): [k/4][128 cols][4]
#define SM_H    32768      // [2][256][8]  double-buffered h, k-major batch-minor
#define SM_G    36864      // [8][128] gate slice per batch
#define SM_HST  37888      // [256] staged h slice (32 units x 8 batches)
#define SM_BAR  38144      // 16 x u64 slice barriers: [buf][src]
#define SM_BYTES ((SM_BAR + 32) * 4)

// -------------------- scratch (device globals; no allocs) -------------------
__device__ float g_x0[(size_t)BT * Emb];
__device__ float g_gx[2ull * BT * 1024];
__device__ float g_y0[(size_t)BT * 512];
__device__ float g_y1[(size_t)BT * 512];
__device__ float g_wt0[2 * 256 * 1024];
__device__ float g_wt1[2 * 256 * 1024];
__device__ float g_em[(size_t)BT * Lnum];
__device__ float g_partial[Bsz];

__device__ __forceinline__ float sigm(float x) { return 1.0f / (1.0f + __expf(-x)); }

__device__ __forceinline__ unsigned smem_u32(const void* p) {
    return (unsigned)__cvta_generic_to_shared(p);
}
__device__ __forceinline__ unsigned mapa_rank(unsigned addr, int rank) {
    unsigned r;
    asm volatile("mapa.shared::cluster.u32 %0, %1, %2;" : "=r"(r) : "r"(addr), "r"(rank));
    return r;
}
__device__ __forceinline__ void st_cluster_f4(unsigned addr, float4 v) {
    asm volatile("st.shared::cluster.v4.f32 [%0], {%1,%2,%3,%4};"
                 :: "r"(addr), "f"(v.x), "f"(v.y), "f"(v.z), "f"(v.w) : "memory");
}
// acquire try_wait with HW-sleep hint (no tight polling)
__device__ __forceinline__ void mbar_wait_acq(unsigned addr, int phase) {
    asm volatile(
        "{\n\t.reg .pred P;\n"
        "WL%=:\n\t"
        "mbarrier.try_wait.parity.acquire.cluster.shared::cta.b64 P, [%0], %1, 0x989680;\n\t"
        "@P bra.uni WD%=;\n\t"
        "bra.uni WL%=;\n"
        "WD%=:\n\t}"
        :: "r"(addr), "r"(phase) : "memory");
}
__device__ __forceinline__ void mbar_arrive_rel(unsigned addr) {
    asm volatile("mbarrier.arrive.release.cluster.shared::cluster.b64 _, [%0];"
                 :: "r"(addr) : "memory");
}
__device__ __forceinline__ void fma2(unsigned long long& acc,
                                     unsigned long long a, unsigned long long b) {
    asm("fma.rn.f32x2 %0, %1, %2, %0;" : "+l"(acc) : "l"(a), "l"(b));
}
__device__ __forceinline__ unsigned long long pack2(float f) {
    unsigned long long r;
    asm("mov.b64 %0, {%1, %1};" : "=l"(r) : "f"(f));
    return r;
}

// -------------------- 1) embedding gather (float4) --------------------------
__global__ void k_embed(const int* __restrict__ ids, const float* __restrict__ emb) {
    int i = blockIdx.x * blockDim.x + threadIdx.x;
    if (i >= BT * (Emb / 4)) return;
    int pos = i >> 6;
    int e4  = i & 63;
    ((float4*)g_x0)[i] = ((const float4*)emb)[(size_t)ids[pos] * (Emb / 4) + e4];
}

// -------- 2) w_hh relayout [2][1024][256] -> [d][rank][k/4][128 cols][4] ----
__global__ void k_trans(const float* __restrict__ w, int layer) {
    int i = blockIdx.x * blockDim.x + threadIdx.x;
    if (i >= 2 * 1024 * 256) return;
    int d   = i >> 18;
    int row = (i >> 8) & 1023;
    int k   = i & 255;
    int g   = row >> 8;
    int r   = (row & 255) >> 5;
    int jj  = row & 31;
    int c   = g * 32 + jj;
    float* dst = layer ? g_wt1 : g_wt0;
    dst[d * 262144 + r * 32768 + (k >> 2) * 512 + c * 4 + (k & 3)] = w[i];
}

// -------------------- 3) gx GEMM (fp32 SIMT) ---------------------------------
__global__ void __launch_bounds__(256) k_gemm(const float* __restrict__ W,
                                              const float* __restrict__ bias,
                                              int layer) {
    __shared__ float As[16][128];
    __shared__ float Ws[16][128];
    const int K = layer ? 512 : 256;
    const float* __restrict__ Ad = layer ? g_y0 : g_x0;
    const int tid = threadIdx.x;
    const int tx = tid & 15, ty = tid >> 4;
    const int m0 = blockIdx.y * 128, n0 = blockIdx.x * 128;
    const int d = blockIdx.z;
    const float* Wd = W + (size_t)d * 1024 * K;
    const float* bd = bias + d * 1024;
    float* Cd = g_gx + (size_t)d * BT * 1024;
    const int lr = tid >> 2;
    const int lc = (tid & 3) * 4;

    float acc[8][8];
#pragma unroll
    for (int i = 0; i < 8; i++)
#pragma unroll
        for (int j = 0; j < 8; j++) acc[i][j] = 0.0f;

    for (int k0 = 0; k0 < K; k0 += 16) {
        float4 a0 = *(const float4*)&Ad[(size_t)(m0 + lr) * K + k0 + lc];
        float4 a1 = *(const float4*)&Ad[(size_t)(m0 + lr + 64) * K + k0 + lc];
        float4 w0 = *(const float4*)&Wd[(size_t)(n0 + lr) * K + k0 + lc];
        float4 w1 = *(const float4*)&Wd[(size_t)(n0 + lr + 64) * K + k0 + lc];
        __syncthreads();
        As[lc + 0][lr] = a0.x; As[lc + 1][lr] = a0.y; As[lc + 2][lr] = a0.z; As[lc + 3][lr] = a0.w;
        As[lc + 0][lr + 64] = a1.x; As[lc + 1][lr + 64] = a1.y; As[lc + 2][lr + 64] = a1.z; As[lc + 3][lr + 64] = a1.w;
        Ws[lc + 0][lr] = w0.x; Ws[lc + 1][lr] = w0.y; Ws[lc + 2][lr] = w0.z; Ws[lc + 3][lr] = w0.w;
        Ws[lc + 0][lr + 64] = w1.x; Ws[lc + 1][lr + 64] = w1.y; Ws[lc + 2][lr + 64] = w1.z; Ws[lc + 3][lr + 64] = w1.w;
        __syncthreads();
#pragma unroll
        for (int kk = 0; kk < 16; kk++) {
            float4 af0 = *(const float4*)&As[kk][ty * 8];
            float4 af1 = *(const float4*)&As[kk][ty * 8 + 4];
            float4 wf0 = *(const float4*)&Ws[kk][tx * 8];
            float4 wf1 = *(const float4*)&Ws[kk][tx * 8 + 4];
            float a[8] = {af0.x, af0.y, af0.z, af0.w, af1.x, af1.y, af1.z, af1.w};
            float w[8] = {wf0.x, wf0.y, wf0.z, wf0.w, wf1.x, wf1.y, wf1.z, wf1.w};
#pragma unroll
            for (int i = 0; i < 8; i++)
#pragma unroll
                for (int j = 0; j < 8; j++) acc[i][j] = fmaf(a[i], w[j], acc[i][j]);
        }
    }
    float bv[8];
#pragma unroll
    for (int j = 0; j < 8; j++) bv[j] = bd[n0 + tx * 8 + j];
#pragma unroll
    for (int i = 0; i < 8; i++) {
        int m = m0 + ty * 8 + i;
        float4 o0 = make_float4(acc[i][0] + bv[0], acc[i][1] + bv[1], acc[i][2] + bv[2], acc[i][3] + bv[3]);
        float4 o1 = make_float4(acc[i][4] + bv[4], acc[i][5] + bv[5], acc[i][6] + bv[6], acc[i][7] + bv[7]);
        *(float4*)&Cd[(size_t)m * 1024 + n0 + tx * 8] = o0;
        *(float4*)&Cd[(size_t)m * 1024 + n0 + tx * 8 + 4] = o1;
    }
}

// -------------------- 4) LSTM recurrence: pipelined per-slice sync ----------
// 8-CTA cluster per (dir, 8-batch group).  Rank owns 32 hidden units.
// Per step: GEMV consumed in 8 chunks ordered (r, r+1, ..., r+7); chunk c>0
// try_waits bar[buf][src] (count 32, arrived by the producing warp's 32 lanes
// with release after their DSMEM stores).  Transfer latency hides under the
// chunks that don't need the slice.  Double-buffered h + dataflow bounds
// skew at 1 step, so 2 barrier sets with parity reuse are safe.
__global__ void __launch_bounds__(256) __cluster_dims__(8, 1, 1)
k_lstm(int layer) {
    extern __shared__ float sm[];
    float* wsm = sm + SM_W;
    float* hb  = sm + SM_H;        // [2][256][8]
    float* gsm = sm + SM_G;        // [8][128]
    float* hst = sm + SM_HST;      // [256] = slice layout [32 units][8 batches]

    const int tid = threadIdx.x;
    const int r   = blockIdx.x & 7;
    const int gid = blockIdx.x >> 3;
    const int d   = gid >> 3;
    const int b0  = (gid & 7) * 8;
    const float* wt = layer ? g_wt1 : g_wt0;
    float* y = layer ? g_y1 : g_y0;
    const float* gxd = g_gx + (size_t)d * BT * 1024;
    const unsigned bar_base = smem_u32(sm + SM_BAR);   // bar(b,src) = +(b*8+src)*8

    // load W slice into smem (float4), zero h buffers, init 16 slice barriers
    {
        const float4* src4 = (const float4*)(wt + d * 262144 + r * 32768);
        float4* dst = (float4*)wsm;
        for (int i = tid; i < 8192; i += 256) dst[i] = src4[i];
        for (int i = tid; i < 2 * 256 * 8; i += 256) hb[i] = 0.0f;
    }
    if (tid < 16)
        asm volatile("mbarrier.init.shared.b64 [%0], %1;"
                     :: "r"(bar_base + tid * 8), "r"(32) : "memory");
    __syncthreads();
    asm volatile("barrier.cluster.arrive.aligned;\n\tbarrier.cluster.wait.aligned;" ::: "memory");

    const int col = tid & 127;     // gate column within rank slice
    const int bp  = tid >> 7;      // batch half: 0 -> b0..b3, 1 -> b4..b7
    const int ub  = tid >> 5;      // update-phase batch
    const int ujj = tid & 31;      // update-phase unit within slice

    // broadcast: warp q (q = tid>>5) services destination rank q; lane j = tid&31
    // sends float4 pair j of this rank's slice into hb[buf][r*32 .. ][..].
    const int q = tid >> 5;
    const int j = tid & 31;
    const unsigned hb_base = smem_u32(hb);
    const unsigned rel0 = (unsigned)((0 * 2048 + r * 256) * 4 + j * 32);
    const unsigned rel1 = (unsigned)((1 * 2048 + r * 256) * 4 + j * 32);
    const unsigned rem0 = mapa_rank(hb_base + rel0, q);
    const unsigned rem1 = mapa_rank(hb_base + rel1, q);
    const unsigned arr0 = mapa_rank(bar_base + (0 * 8 + r) * 8, q);
    const unsigned arr1 = mapa_rank(bar_base + (1 * 8 + r) * 8, q);

    const int gxcol = (col >> 5) * 256 + r * 32 + (col & 31);
    const float4* wsm4 = (const float4*)wsm;
    float creg = 0.0f;

    for (int s = 0; s < Tlen; s++) {
        const int t = d ? (Tlen - 1 - s) : s;
        const int b = s & 1;
        const int ph = ((s - 1) >> 1) & 1;          // parity for this step's waits

        // gx prefetch (independent; hides DRAM latency under chunk compute)
        const size_t gb = ((size_t)(b0 + bp * 4) * Tlen + t) * 1024 + gxcol;
        float gx0 = gxd[gb];
        float gx1 = gxd[gb + (size_t)Tlen * 1024];
        float gx2 = gxd[gb + (size_t)Tlen * 2048];
        float gx3 = gxd[gb + (size_t)Tlen * 3072];

        unsigned long long acc01 = 0ull, acc23 = 0ull;
#pragma unroll
        for (int c = 0; c < 8; c++) {
            const int src = (r + c) & 7;
            if (c > 0 && s > 0)
                mbar_wait_acq(bar_base + (b * 8 + src) * 8, ph);
            const float4* wblk = wsm4 + src * 8 * 128 + col;
            const float* hblk = hb + b * 2048 + src * 256 + bp * 4;
#pragma unroll
            for (int kk = 0; kk < 8; kk++) {
                float4 w4 = wblk[kk * 128];
                const float* hrow = hblk + kk * 32;
                ulonglong2 h0 = *(const ulonglong2*)(hrow);
                ulonglong2 h1 = *(const ulonglong2*)(hrow + 8);
                ulonglong2 h2 = *(const ulonglong2*)(hrow + 16);
                ulonglong2 h3 = *(const ulonglong2*)(hrow + 24);
                unsigned long long w0 = pack2(w4.x);
                unsigned long long w1 = pack2(w4.y);
                unsigned long long w2 = pack2(w4.z);
                unsigned long long w3 = pack2(w4.w);
                fma2(acc01, w0, h0.x); fma2(acc23, w0, h0.y);
                fma2(acc01, w1, h1.x); fma2(acc23, w1, h1.y);
                fma2(acc01, w2, h2.x); fma2(acc23, w2, h2.y);
                fma2(acc01, w3, h3.x); fma2(acc23, w3, h3.y);
            }
        }
        {
            float a0, a1, a2, a3;
            asm("mov.b64 {%0,%1}, %2;" : "=f"(a0), "=f"(a1) : "l"(acc01));
            asm("mov.b64 {%0,%1}, %2;" : "=f"(a2), "=f"(a3) : "l"(acc23));
            gsm[(bp * 4 + 0) * 128 + col] = a0 + gx0;
            gsm[(bp * 4 + 1) * 128 + col] = a1 + gx1;
            gsm[(bp * 4 + 2) * 128 + col] = a2 + gx2;
            gsm[(bp * 4 + 3) * 128 + col] = a3 + gx3;
        }
        __syncthreads();

        // gate nonlinearity + state update; thread owns (ub, ujj), c in reg
        {
            float gi = gsm[ub * 128 + ujj];
            float gf = gsm[ub * 128 + 32 + ujj];
            float gg = gsm[ub * 128 + 64 + ujj];
            float go = gsm[ub * 128 + 96 + ujj];
            creg = sigm(gf) * creg + sigm(gi) * tanhf(gg);
            float h = sigm(go) * tanhf(creg);
            hst[ujj * 8 + ub] = h;
            y[((size_t)(b0 + ub) * Tlen + t) * 512 + d * 256 + r * 32 + ujj] = h;
        }
        __syncthreads();

        // broadcast this rank's slice for step s+1 (buffer nb) + release-arrive
        if (s + 1 < Tlen) {
            const int nb = (s + 1) & 1;
            float4 v0 = *(const float4*)&hst[j * 8];
            float4 v1 = *(const float4*)&hst[j * 8 + 4];
            unsigned ra = nb ? rem1 : rem0;
            st_cluster_f4(ra, v0);
            st_cluster_f4(ra + 16, v1);
            mbar_arrive_rel(nb ? arr1 : arr0);
        }
        __syncthreads();   // local visibility of own-slice stores + hst reuse
    }

    // no CTA may exit while peers' remote stores into its SMEM are in flight
    asm volatile("barrier.cluster.arrive.aligned;\n\tbarrier.cluster.wait.aligned;" ::: "memory");
}

// -------------------- 5) emissions = y1 @ lin_w^T + lin_b -------------------
__global__ void __launch_bounds__(256) k_linear(const float* __restrict__ lw,
                                                const float* __restrict__ lb) {
    __shared__ float ws[Lnum * 512];
    __shared__ float bs[Lnum];
    const int tid = threadIdx.x;
    for (int i = tid; i < Lnum * 512; i += 256) ws[i] = lw[i];
    if (tid < Lnum) bs[tid] = lb[tid];
    __syncthreads();
    const int warp = tid >> 5, lane = tid & 31;
    const int pos = blockIdx.x * 8 + warp;
    const float* yp = g_y1 + (size_t)pos * 512;
    float acc[Lnum];
#pragma unroll
    for (int l = 0; l < Lnum; l++) acc[l] = 0.0f;
    for (int k = lane; k < 512; k += 32) {
        float yv = yp[k];
#pragma unroll
        for (int l = 0; l < Lnum; l++) acc[l] = fmaf(yv, ws[l * 512 + k], acc[l]);
    }
#pragma unroll
    for (int l = 0; l < Lnum; l++)
#pragma unroll
        for (int o = 16; o > 0; o >>= 1) acc[l] += __shfl_xor_sync(0xffffffffu, acc[l], o);
    if (lane < Lnum) g_em[(size_t)pos * Lnum + lane] = acc[lane] + bs[lane];
}

// -------------------- 6) CRF NLL --------------------------------------------
__global__ void k_crf(const int* __restrict__ labels, const int* __restrict__ mask,
                      const float* __restrict__ trans, const float* __restrict__ startt,
                      const float* __restrict__ endt) {
    const int b = blockIdx.x;
    const int lane = threadIdx.x;
    __shared__ float salpha[Lnum];
    const float* em = g_em + (size_t)b * Tlen * Lnum;
    const int* lab = labels + b * Tlen;
    const int* msk = mask + b * Tlen;
    const int j = (lane < Lnum) ? lane : 0;

    float tr[Lnum];
#pragma unroll
    for (int i = 0; i < Lnum; i++) tr[i] = trans[i * Lnum + j];

    int mcount = 0;
    for (int t = lane; t < Tlen; t += 32) mcount += msk[t];
#pragma unroll
    for (int o = 16; o > 0; o >>= 1) mcount += __shfl_xor_sync(0xffffffffu, mcount, o);
    float sc = 0.0f;
    for (int t = lane + 1; t < Tlen; t += 32)
        if (msk[t]) sc += trans[lab[t - 1] * Lnum + lab[t]] + em[t * Lnum + lab[t]];
#pragma unroll
    for (int o = 16; o > 0; o >>= 1) sc += __shfl_xor_sync(0xffffffffu, sc, o);

    float alpha = startt[j] + em[j];
    for (int t = 1; t < Tlen; t++) {
        if (lane < Lnum) salpha[lane] = alpha;
        __syncwarp();
        float vs[Lnum];
        float m = -1e30f;
#pragma unroll
        for (int i = 0; i < Lnum; i++) {
            vs[i] = salpha[i] + tr[i];
            m = fmaxf(m, vs[i]);
        }
        float ssum = 0.0f;
#pragma unroll
        for (int i = 0; i < Lnum; i++) ssum += __expf(vs[i] - m);
        float na = m + __logf(ssum) + em[t * Lnum + j];
        if (msk[t]) alpha = na;
        __syncwarp();
    }
    float v = (lane < Lnum) ? alpha + endt[lane] : -1e30f;
    float mm = v;
#pragma unroll
    for (int o = 16; o > 0; o >>= 1) mm = fmaxf(mm, __shfl_xor_sync(0xffffffffu, mm, o));
    float e = (lane < Lnum) ? __expf(v - mm) : 0.0f;
#pragma unroll
    for (int o = 16; o > 0; o >>= 1) e += __shfl_xor_sync(0xffffffffu, e, o);
    float logZ = mm + __logf(e);

    if (lane == 0) {
        sc += startt[lab[0]] + em[lab[0]] + endt[lab[mcount - 1]];
        g_partial[b] = logZ - sc;
    }
}

// -------------------- 7) mean reduce ----------------------------------------
__global__ void k_final(float* __restrict__ out) {
    __shared__ float s[Bsz];
    const int tid = threadIdx.x;
    s[tid] = g_partial[tid];
    __syncthreads();
    for (int o = 32; o > 0; o >>= 1) {
        if (tid < o) s[tid] += s[tid + o];
        __syncthreads();
    }
    if (tid == 0) out[0] = s[0] * (1.0f / (float)Bsz);
}

// ---------------------------------------------------------------------------
extern "C" void kernel_launch(void* const* d_in, const int* in_sizes, int n_in,
                              void* d_out, int out_size) {
    (void)in_sizes; (void)n_in; (void)out_size;
    const int*   input_ids = (const int*)d_in[0];
    const int*   attn      = (const int*)d_in[1];
    const int*   labels    = (const int*)d_in[2];
    const float* emb       = (const float*)d_in[3];
    const float* w_ih0     = (const float*)d_in[4];
    const float* w_hh0     = (const float*)d_in[5];
    const float* b0        = (const float*)d_in[6];
    const float* w_ih1     = (const float*)d_in[7];
    const float* w_hh1     = (const float*)d_in[8];
    const float* b1        = (const float*)d_in[9];
    const float* lin_w     = (const float*)d_in[10];
    const float* lin_b     = (const float*)d_in[11];
    const float* trans     = (const float*)d_in[12];
    const float* startt    = (const float*)d_in[13];
    const float* endt      = (const float*)d_in[14];
    float* out = (float*)d_out;

    cudaFuncSetAttribute(k_lstm, cudaFuncAttributeMaxDynamicSharedMemorySize, SM_BYTES);

    k_embed<<<(BT * (Emb / 4) + 255) / 256, 256>>>(input_ids, emb);
    k_trans<<<(2 * 1024 * 256 + 255) / 256, 256>>>(w_hh0, 0);
    k_trans<<<(2 * 1024 * 256 + 255) / 256, 256>>>(w_hh1, 1);

    k_gemm<<<dim3(8, 256, 2), 256>>>(w_ih0, b0, 0);
    k_lstm<<<128, 256, SM_BYTES>>>(0);

    k_gemm<<<dim3(8, 256, 2), 256>>>(w_ih1, b1, 1);
    k_lstm<<<128, 256, SM_BYTES>>>(1);

    k_linear<<<BT / 8, 256>>>(lin_w, lin_b);
    k_crf<<<Bsz, 32>>>(labels, attn, trans, startt, endt);
    k_final<<<1, 64>>>(out);
}

// round 9
// speedup vs baseline: 1.2432x; 1.2432x over previous
#include <cuda_runtime.h>
#include <cuda_bf16.h>

// ---------------------------------------------------------------------------
// BiLSTM-CRF forward loss.  B=64, T=512, V=50000, E=256, H=256, L=9.
// embed -> gemm(gx,l0) -> lstm(l0: 128 plain CTAs, L2 h-exchange, flags)
//       -> gemm(gx,l1) -> lstm(l1) -> linear -> CRF NLL -> mean.
// ---------------------------------------------------------------------------

#define Bsz  64
#define Tlen 512
#define Emb  256
#define Hd   256
#define Lnum 9
#define BT   (Bsz * Tlen)   // 32768

// dynamic smem layout for k_lstm (float offsets)
#define SM_W    0          // [32768] w slice (rank): [k/4][128 cols][4]
#define SM_H    32768      // [256][8]  h_local, k-major batch-minor (single buf)
#define SM_G    34816      // [8][128]  gate slice per batch
#define SM_HST  35840      // [256]     staged own h slice [ujj][ub]
#define SM_BYTES ((SM_HST + 256) * 4)   // 144,384 B

// -------------------- scratch (device globals; no allocs) -------------------
__device__ float g_x0[(size_t)BT * Emb];
__device__ float g_gx[2ull * BT * 1024];
__device__ float g_y0[(size_t)BT * 512];
__device__ float g_y1[(size_t)BT * 512];
__device__ float g_wt0[2 * 256 * 1024];
__device__ float g_wt1[2 * 256 * 1024];
__device__ float g_em[(size_t)BT * Lnum];
__device__ float g_partial[Bsz];
__device__ float g_dummy[32];
// h exchange: [d][g][buf][256 units][8 batches]  (+ flags, monotonic counters)
__device__ float g_hx[2 * 8 * 2 * 2048];
__device__ int   g_flag[2 * 8 * 8];

__device__ __forceinline__ float sigm(float x) { return 1.0f / (1.0f + __expf(-x)); }

__device__ __forceinline__ void fma2(unsigned long long& acc,
                                     unsigned long long a, unsigned long long b) {
    asm("fma.rn.f32x2 %0, %1, %2, %0;" : "+l"(acc) : "l"(a), "l"(b));
}
__device__ __forceinline__ unsigned long long pack2(float f) {
    unsigned long long r;
    asm("mov.b64 %0, {%1, %1};" : "=l"(r) : "f"(f));
    return r;
}
__device__ __forceinline__ void flag_store_release(int* p, int v) {
    asm volatile("st.release.gpu.s32 [%0], %1;" :: "l"(p), "r"(v) : "memory");
}
__device__ __forceinline__ int flag_load_acquire(const int* p) {
    int v;
    asm volatile("ld.acquire.gpu.s32 %0, [%1];" : "=r"(v) : "l"(p) : "memory");
    return v;
}

// -------------------- 1) embedding gather (float4) --------------------------
__global__ void k_embed(const int* __restrict__ ids, const float* __restrict__ emb) {
    int i = blockIdx.x * blockDim.x + threadIdx.x;
    if (i >= BT * (Emb / 4)) return;
    int pos = i >> 6;
    int e4  = i & 63;
    ((float4*)g_x0)[i] = ((const float4*)emb)[(size_t)ids[pos] * (Emb / 4) + e4];
}

// -------- 2) w_hh relayout [2][1024][256] -> [d][rank][k/4][128 cols][4] ----
// Also zeroes the exchange flags (runs twice, both before any k_lstm).
__global__ void k_trans(const float* __restrict__ w, int layer) {
    int i = blockIdx.x * blockDim.x + threadIdx.x;
    if (i < 2 * 8 * 8) g_flag[i] = 0;
    if (i >= 2 * 1024 * 256) return;
    int d   = i >> 18;
    int row = (i >> 8) & 1023;
    int k   = i & 255;
    int g   = row >> 8;
    int r   = (row & 255) >> 5;
    int jj  = row & 31;
    int c   = g * 32 + jj;
    float* dst = layer ? g_wt1 : g_wt0;
    dst[d * 262144 + r * 32768 + (k >> 2) * 512 + c * 4 + (k & 3)] = w[i];
}

// -------------------- dummy: shifts ncu -s 5 capture onto k_lstm ------------
__global__ void k_dummy() {
    if (threadIdx.x < 32) g_dummy[threadIdx.x] = (float)threadIdx.x;
}

// -------------------- 3) gx GEMM (fp32 SIMT) ---------------------------------
__global__ void __launch_bounds__(256) k_gemm(const float* __restrict__ W,
                                              const float* __restrict__ bias,
                                              int layer) {
    __shared__ float As[16][128];
    __shared__ float Ws[16][128];
    const int K = layer ? 512 : 256;
    const float* __restrict__ Ad = layer ? g_y0 : g_x0;
    const int tid = threadIdx.x;
    const int tx = tid & 15, ty = tid >> 4;
    const int m0 = blockIdx.y * 128, n0 = blockIdx.x * 128;
    const int d = blockIdx.z;
    const float* Wd = W + (size_t)d * 1024 * K;
    const float* bd = bias + d * 1024;
    float* Cd = g_gx + (size_t)d * BT * 1024;
    const int lr = tid >> 2;
    const int lc = (tid & 3) * 4;

    float acc[8][8];
#pragma unroll
    for (int i = 0; i < 8; i++)
#pragma unroll
        for (int j = 0; j < 8; j++) acc[i][j] = 0.0f;

    for (int k0 = 0; k0 < K; k0 += 16) {
        float4 a0 = *(const float4*)&Ad[(size_t)(m0 + lr) * K + k0 + lc];
        float4 a1 = *(const float4*)&Ad[(size_t)(m0 + lr + 64) * K + k0 + lc];
        float4 w0 = *(const float4*)&Wd[(size_t)(n0 + lr) * K + k0 + lc];
        float4 w1 = *(const float4*)&Wd[(size_t)(n0 + lr + 64) * K + k0 + lc];
        __syncthreads();
        As[lc + 0][lr] = a0.x; As[lc + 1][lr] = a0.y; As[lc + 2][lr] = a0.z; As[lc + 3][lr] = a0.w;
        As[lc + 0][lr + 64] = a1.x; As[lc + 1][lr + 64] = a1.y; As[lc + 2][lr + 64] = a1.z; As[lc + 3][lr + 64] = a1.w;
        Ws[lc + 0][lr] = w0.x; Ws[lc + 1][lr] = w0.y; Ws[lc + 2][lr] = w0.z; Ws[lc + 3][lr] = w0.w;
        Ws[lc + 0][lr + 64] = w1.x; Ws[lc + 1][lr + 64] = w1.y; Ws[lc + 2][lr + 64] = w1.z; Ws[lc + 3][lr + 64] = w1.w;
        __syncthreads();
#pragma unroll
        for (int kk = 0; kk < 16; kk++) {
            float4 af0 = *(const float4*)&As[kk][ty * 8];
            float4 af1 = *(const float4*)&As[kk][ty * 8 + 4];
            float4 wf0 = *(const float4*)&Ws[kk][tx * 8];
            float4 wf1 = *(const float4*)&Ws[kk][tx * 8 + 4];
            float a[8] = {af0.x, af0.y, af0.z, af0.w, af1.x, af1.y, af1.z, af1.w};
            float w[8] = {wf0.x, wf0.y, wf0.z, wf0.w, wf1.x, wf1.y, wf1.z, wf1.w};
#pragma unroll
            for (int i = 0; i < 8; i++)
#pragma unroll
                for (int j = 0; j < 8; j++) acc[i][j] = fmaf(a[i], w[j], acc[i][j]);
        }
    }
    float bv[8];
#pragma unroll
    for (int j = 0; j < 8; j++) bv[j] = bd[n0 + tx * 8 + j];
#pragma unroll
    for (int i = 0; i < 8; i++) {
        int m = m0 + ty * 8 + i;
        float4 o0 = make_float4(acc[i][0] + bv[0], acc[i][1] + bv[1], acc[i][2] + bv[2], acc[i][3] + bv[3]);
        float4 o1 = make_float4(acc[i][4] + bv[4], acc[i][5] + bv[5], acc[i][6] + bv[6], acc[i][7] + bv[7]);
        *(float4*)&Cd[(size_t)m * 1024 + n0 + tx * 8] = o0;
        *(float4*)&Cd[(size_t)m * 1024 + n0 + tx * 8 + 4] = o1;
    }
}

// -------------------- 4) LSTM recurrence: plain CTAs, L2 h-exchange ---------
// 128 CTAs (one wave): bx = d*64 + r*8 + g.  Rank r owns 32 hidden units
// (128 gate cols) for batch group g (8 batches).  W slice in SMEM.
// Per step: GEMV(h_local) -> gates -> update -> own slice to h_local + staged;
// publish slice to g_hx[buf] in L2 + release flag (monotonic, layer-based);
// peers acquire-spin then __ldcg the 7 remote slices into h_local.
__global__ void __launch_bounds__(256) k_lstm(int layer) {
    extern __shared__ float sm[];
    float* wsm = sm + SM_W;
    float* hl  = sm + SM_H;        // [256][8]
    float* gsm = sm + SM_G;        // [8][128]
    float* hst = sm + SM_HST;      // [256] = [ujj][ub]

    const int tid = threadIdx.x;
    const int bx  = blockIdx.x;
    const int d   = bx >> 6;
    const int r   = (bx >> 3) & 7;
    const int g   = bx & 7;
    const int b0  = g * 8;
    const float* wt = layer ? g_wt1 : g_wt0;
    float* y = layer ? g_y1 : g_y0;
    const float* gxd = g_gx + (size_t)d * BT * 1024;
    const int beta = layer * Tlen;                    // flag base for this layer

    float*  hx_grp   = g_hx + ((d * 8 + g) * 2) * 2048;   // + buf*2048
    int*    flag_grp = g_flag + (d * 8 + g) * 8;           // + src

    // load W slice into smem, zero h_local
    {
        const float4* src4 = (const float4*)(wt + d * 262144 + r * 32768);
        float4* dst = (float4*)wsm;
        for (int i = tid; i < 8192; i += 256) dst[i] = src4[i];
        for (int i = tid; i < 2048; i += 256) hl[i] = 0.0f;
    }
    __syncthreads();

    const int col = tid & 127;     // gate column within rank slice
    const int bp  = tid >> 7;      // batch half: 0 -> b0..b3, 1 -> b4..b7
    const int ub  = tid >> 5;      // update-phase batch
    const int ujj = tid & 31;      // update-phase unit within slice
    const int wrp = tid >> 5;      // warp id (peer-load phase: warp w loads slice w)
    const int lane = tid & 31;

    const int gxcol = (col >> 5) * 256 + r * 32 + (col & 31);
    const float4* wsm4 = (const float4*)wsm;
    float4* hl4 = (float4*)hl;
    float creg = 0.0f;

    for (int s = 0; s < Tlen; s++) {
        const int t = d ? (Tlen - 1 - s) : s;

        // gx prefetch for this step (issue before exchange; DRAM latency hides)
        const size_t gb = ((size_t)(b0 + bp * 4) * Tlen + t) * 1024 + gxcol;
        float gx0 = gxd[gb];
        float gx1 = gxd[gb + (size_t)Tlen * 1024];
        float gx2 = gxd[gb + (size_t)Tlen * 2048];
        float gx3 = gxd[gb + (size_t)Tlen * 3072];

        // ---- exchange-in: wait peers' flags, pull 7 slices from L2 ----
        if (s > 0) {
            if (tid < 8) {
                const int* fp = flag_grp + tid;
                while (flag_load_acquire(fp) < beta + s) { }
            }
            __syncthreads();
            const float4* hxb = (const float4*)(hx_grp + (s & 1) * 2048);
            if (wrp != r) {
                hl4[wrp * 64 + lane]      = __ldcg(hxb + wrp * 64 + lane);
                hl4[wrp * 64 + lane + 32] = __ldcg(hxb + wrp * 64 + lane + 32);
            }
            __syncthreads();
        }

        // ---- GEMV: gates[col][4 batches of bp half] ----
        unsigned long long acc01 = 0ull, acc23 = 0ull;
        const float* hc = hl + bp * 4;
#pragma unroll 2
        for (int kk = 0; kk < 64; kk++) {
            float4 w4 = wsm4[kk * 128 + col];
            const float* hrow = hc + kk * 32;
            ulonglong2 h0 = *(const ulonglong2*)(hrow);
            ulonglong2 h1 = *(const ulonglong2*)(hrow + 8);
            ulonglong2 h2 = *(const ulonglong2*)(hrow + 16);
            ulonglong2 h3 = *(const ulonglong2*)(hrow + 24);
            unsigned long long w0 = pack2(w4.x);
            unsigned long long w1 = pack2(w4.y);
            unsigned long long w2 = pack2(w4.z);
            unsigned long long w3 = pack2(w4.w);
            fma2(acc01, w0, h0.x); fma2(acc23, w0, h0.y);
            fma2(acc01, w1, h1.x); fma2(acc23, w1, h1.y);
            fma2(acc01, w2, h2.x); fma2(acc23, w2, h2.y);
            fma2(acc01, w3, h3.x); fma2(acc23, w3, h3.y);
        }
        {
            float a0, a1, a2, a3;
            asm("mov.b64 {%0,%1}, %2;" : "=f"(a0), "=f"(a1) : "l"(acc01));
            asm("mov.b64 {%0,%1}, %2;" : "=f"(a2), "=f"(a3) : "l"(acc23));
            gsm[(bp * 4 + 0) * 128 + col] = a0 + gx0;
            gsm[(bp * 4 + 1) * 128 + col] = a1 + gx1;
            gsm[(bp * 4 + 2) * 128 + col] = a2 + gx2;
            gsm[(bp * 4 + 3) * 128 + col] = a3 + gx3;
        }
        __syncthreads();

        // ---- update: thread owns (ub, ujj); c in register ----
        {
            float gi = gsm[ub * 128 + ujj];
            float gf = gsm[ub * 128 + 32 + ujj];
            float gg = gsm[ub * 128 + 64 + ujj];
            float go = gsm[ub * 128 + 96 + ujj];
            creg = sigm(gf) * creg + sigm(gi) * tanhf(gg);
            float h = sigm(go) * tanhf(creg);
            hst[ujj * 8 + ub] = h;
            hl[(r * 32 + ujj) * 8 + ub] = h;          // own slice, next step
            y[((size_t)(b0 + ub) * Tlen + t) * 512 + d * 256 + r * 32 + ujj] = h;
        }
        __syncthreads();

        // ---- exchange-out: publish own slice for step s+1 ----
        if (s + 1 < Tlen) {
            float4* hxn = (float4*)(hx_grp + ((s + 1) & 1) * 2048);
            if (tid < 64) hxn[r * 64 + tid] = ((const float4*)hst)[tid];
            __syncthreads();
            if (tid == 0) {
                __threadfence();
                flag_store_release(flag_grp + r, beta + s + 1);
            }
        }
    }
}

// -------------------- 5) emissions = y1 @ lin_w^T + lin_b -------------------
__global__ void __launch_bounds__(256) k_linear(const float* __restrict__ lw,
                                                const float* __restrict__ lb) {
    __shared__ float ws[Lnum * 512];
    __shared__ float bs[Lnum];
    const int tid = threadIdx.x;
    for (int i = tid; i < Lnum * 512; i += 256) ws[i] = lw[i];
    if (tid < Lnum) bs[tid] = lb[tid];
    __syncthreads();
    const int warp = tid >> 5, lane = tid & 31;
    const int pos = blockIdx.x * 8 + warp;
    const float* yp = g_y1 + (size_t)pos * 512;
    float acc[Lnum];
#pragma unroll
    for (int l = 0; l < Lnum; l++) acc[l] = 0.0f;
    for (int k = lane; k < 512; k += 32) {
        float yv = yp[k];
#pragma unroll
        for (int l = 0; l < Lnum; l++) acc[l] = fmaf(yv, ws[l * 512 + k], acc[l]);
    }
#pragma unroll
    for (int l = 0; l < Lnum; l++)
#pragma unroll
        for (int o = 16; o > 0; o >>= 1) acc[l] += __shfl_xor_sync(0xffffffffu, acc[l], o);
    if (lane < Lnum) g_em[(size_t)pos * Lnum + lane] = acc[lane] + bs[lane];
}

// -------------------- 6) CRF NLL --------------------------------------------
__global__ void k_crf(const int* __restrict__ labels, const int* __restrict__ mask,
                      const float* __restrict__ trans, const float* __restrict__ startt,
                      const float* __restrict__ endt) {
    const int b = blockIdx.x;
    const int lane = threadIdx.x;
    __shared__ float salpha[Lnum];
    const float* em = g_em + (size_t)b * Tlen * Lnum;
    const int* lab = labels + b * Tlen;
    const int* msk = mask + b * Tlen;
    const int j = (lane < Lnum) ? lane : 0;

    float tr[Lnum];
#pragma unroll
    for (int i = 0; i < Lnum; i++) tr[i] = trans[i * Lnum + j];

    int mcount = 0;
    for (int t = lane; t < Tlen; t += 32) mcount += msk[t];
#pragma unroll
    for (int o = 16; o > 0; o >>= 1) mcount += __shfl_xor_sync(0xffffffffu, mcount, o);
    float sc = 0.0f;
    for (int t = lane + 1; t < Tlen; t += 32)
        if (msk[t]) sc += trans[lab[t - 1] * Lnum + lab[t]] + em[t * Lnum + lab[t]];
#pragma unroll
    for (int o = 16; o > 0; o >>= 1) sc += __shfl_xor_sync(0xffffffffu, sc, o);

    float alpha = startt[j] + em[j];
    for (int t = 1; t < Tlen; t++) {
        if (lane < Lnum) salpha[lane] = alpha;
        __syncwarp();
        float vs[Lnum];
        float m = -1e30f;
#pragma unroll
        for (int i = 0; i < Lnum; i++) {
            vs[i] = salpha[i] + tr[i];
            m = fmaxf(m, vs[i]);
        }
        float ssum = 0.0f;
#pragma unroll
        for (int i = 0; i < Lnum; i++) ssum += __expf(vs[i] - m);
        float na = m + __logf(ssum) + em[t * Lnum + j];
        if (msk[t]) alpha = na;
        __syncwarp();
    }
    float v = (lane < Lnum) ? alpha + endt[lane] : -1e30f;
    float mm = v;
#pragma unroll
    for (int o = 16; o > 0; o >>= 1) mm = fmaxf(mm, __shfl_xor_sync(0xffffffffu, mm, o));
    float e = (lane < Lnum) ? __expf(v - mm) : 0.0f;
#pragma unroll
    for (int o = 16; o > 0; o >>= 1) e += __shfl_xor_sync(0xffffffffu, e, o);
    float logZ = mm + __logf(e);

    if (lane == 0) {
        sc += startt[lab[0]] + em[lab[0]] + endt[lab[mcount - 1]];
        g_partial[b] = logZ - sc;
    }
}

// -------------------- 7) mean reduce ----------------------------------------
__global__ void k_final(float* __restrict__ out) {
    __shared__ float s[Bsz];
    const int tid = threadIdx.x;
    s[tid] = g_partial[tid];
    __syncthreads();
    for (int o = 32; o > 0; o >>= 1) {
        if (tid < o) s[tid] += s[tid + o];
        __syncthreads();
    }
    if (tid == 0) out[0] = s[0] * (1.0f / (float)Bsz);
}

// ---------------------------------------------------------------------------
extern "C" void kernel_launch(void* const* d_in, const int* in_sizes, int n_in,
                              void* d_out, int out_size) {
    (void)in_sizes; (void)n_in; (void)out_size;
    const int*   input_ids = (const int*)d_in[0];
    const int*   attn      = (const int*)d_in[1];
    const int*   labels    = (const int*)d_in[2];
    const float* emb       = (const float*)d_in[3];
    const float* w_ih0     = (const float*)d_in[4];
    const float* w_hh0     = (const float*)d_in[5];
    const float* b0        = (const float*)d_in[6];
    const float* w_ih1     = (const float*)d_in[7];
    const float* w_hh1     = (const float*)d_in[8];
    const float* b1        = (const float*)d_in[9];
    const float* lin_w     = (const float*)d_in[10];
    const float* lin_b     = (const float*)d_in[11];
    const float* trans     = (const float*)d_in[12];
    const float* startt    = (const float*)d_in[13];
    const float* endt      = (const float*)d_in[14];
    float* out = (float*)d_out;

    cudaFuncSetAttribute(k_lstm, cudaFuncAttributeMaxDynamicSharedMemorySize, SM_BYTES);

    k_embed<<<(BT * (Emb / 4) + 255) / 256, 256>>>(input_ids, emb);    // 0
    k_trans<<<(2 * 1024 * 256 + 255) / 256, 256>>>(w_hh0, 0);          // 1
    k_trans<<<(2 * 1024 * 256 + 255) / 256, 256>>>(w_hh1, 1);          // 2
    k_dummy<<<1, 32>>>();                                              // 3

    k_gemm<<<dim3(8, 256, 2), 256>>>(w_ih0, b0, 0);                    // 4
    k_lstm<<<128, 256, SM_BYTES>>>(0);                                 // 5 <- ncu -s 5

    k_gemm<<<dim3(8, 256, 2), 256>>>(w_ih1, b1, 1);
    k_lstm<<<128, 256, SM_BYTES>>>(1);

    k_linear<<<BT / 8, 256>>>(lin_w, lin_b);
    k_crf<<<Bsz, 32>>>(labels, attn, trans, startt, endt);
    k_final<<<1, 64>>>(out);
}